// round 4
// baseline (speedup 1.0000x reference)
#include <cuda_runtime.h>
#include <cstdint>

#define NN 200000
#define NE 6400000
#define NL 10
#define NB_N 782          // ceil(NN/256)

// ---------------- scratch (static __device__, no allocs) -------------------
__device__ int    g_csr[NE];       // src ids, grouped by dst (25.6 MB)
__device__ int    g_row[NN + 1];   // CSR row pointers
__device__ int    g_cursor[NN];    // fill cursors
__device__ int    g_deg[NN];       // in-degree (excl. self-loop)
__device__ float  g_dis[NN];       // rsqrt(deg+1)
__device__ float2 g_t[2][NN];      // ping-pong: t = dis * (h @ W)
__device__ int    g_part[1024];    // scan partials
__device__ int    g_is64;

// ---- dtype sniff: int64 indices < 2^31 have all-zero odd 32-bit words -----
__global__ void k_detect(const unsigned int* __restrict__ w) {
    int lane = threadIdx.x;
    unsigned int acc = 0;
    for (int i = 0; i < 32; i++) acc |= w[2 * (lane * 32 + i) + 1];
    unsigned mask = __ballot_sync(0xFFFFFFFFu, acc != 0);
    if (lane == 0) g_is64 = (mask == 0) ? 1 : 0;
}

__global__ void k_zero() {
    int i = blockIdx.x * blockDim.x + threadIdx.x;
    if (i < NN) g_deg[i] = 0;
}

// count in-degree at dst
__global__ void k_deg(const void* __restrict__ ei_raw) {
    int e = blockIdx.x * blockDim.x + threadIdx.x;
    if (e >= NE) return;
    int d;
    if (g_is64) d = (int)((const long long*)ei_raw)[NE + e];
    else        d = ((const int*)ei_raw)[NE + e];
    atomicAdd(&g_deg[d], 1);
}

// ---- 3-kernel exclusive scan of g_deg -> g_row ----------------------------
__global__ void k_scan1() {
    __shared__ int sm[256];
    int i = blockIdx.x * 256 + threadIdx.x;
    int v = (i < NN) ? g_deg[i] : 0;
    sm[threadIdx.x] = v;
    __syncthreads();
    for (int off = 1; off < 256; off <<= 1) {
        int t = (threadIdx.x >= off) ? sm[threadIdx.x - off] : 0;
        __syncthreads();
        sm[threadIdx.x] += t;
        __syncthreads();
    }
    if (i < NN) g_row[i] = sm[threadIdx.x] - v;
    if (threadIdx.x == 255) g_part[blockIdx.x] = sm[255];
}

__global__ void k_scan2() {
    __shared__ int sm[1024];
    int t = threadIdx.x;
    int v = (t < NB_N) ? g_part[t] : 0;
    sm[t] = v;
    __syncthreads();
    for (int off = 1; off < 1024; off <<= 1) {
        int u = (t >= off) ? sm[t - off] : 0;
        __syncthreads();
        sm[t] += u;
        __syncthreads();
    }
    if (t < NB_N) g_part[t] = sm[t] - v;
}

__global__ void k_scan3() {
    int i = blockIdx.x * blockDim.x + threadIdx.x;
    if (i < NN) {
        int r = g_row[i] + g_part[i >> 8];
        g_row[i] = r;
        g_cursor[i] = r;
    }
    if (i == 0) g_row[NN] = NE;
}

// scatter src ids into dst-grouped CSR
__global__ void k_fill(const void* __restrict__ ei_raw) {
    int e = blockIdx.x * blockDim.x + threadIdx.x;
    if (e >= NE) return;
    int s, d;
    if (g_is64) {
        const long long* ei = (const long long*)ei_raw;
        s = (int)ei[e];  d = (int)ei[NE + e];
    } else {
        const int* ei = (const int*)ei_raw;
        s = ei[e];       d = ei[NE + e];
    }
    int pos = atomicAdd(&g_cursor[d], 1);
    g_csr[pos] = s;
}

// dis = rsqrt(deg+1); t0 = dis * (x @ W0)
__global__ void k_init(const float* __restrict__ x, const float* __restrict__ Ws) {
    int n = blockIdx.x * blockDim.x + threadIdx.x;
    if (n >= NN) return;
    float ds = rsqrtf((float)(g_deg[n] + 1));
    g_dis[n] = ds;
    float w00 = __ldg(&Ws[0]), w01 = __ldg(&Ws[1]);
    float w10 = __ldg(&Ws[2]), w11 = __ldg(&Ws[3]);
    float hx = x[2 * n], hy = x[2 * n + 1];
    g_t[0][n] = make_float2(ds * (hx * w00 + hy * w10),
                            ds * (hx * w01 + hy * w11));
}

// Fused layer, WARP-PER-NODE:
//   lanes stride the node's CSR row (coalesced), gather t[src], butterfly-
//   reduce, lane 0 applies self-loop + dis + bias + next-layer 2x2 (or output).
__global__ void __launch_bounds__(256) k_layer(
        const float* __restrict__ Ws, const float* __restrict__ bs,
        int layer, int inbuf, float* __restrict__ out) {
    int gwarp = (blockIdx.x * blockDim.x + threadIdx.x) >> 5;
    int lane  = threadIdx.x & 31;
    if (gwarp >= NN) return;
    int n = gwarp;

    const float2* __restrict__ tin = g_t[inbuf];
    int beg = g_row[n];            // warp-uniform address -> single broadcast
    int end = g_row[n + 1];

    float ax = 0.f, ay = 0.f;
    for (int j = beg + lane; j < end; j += 32) {
        int s = g_csr[j];          // coalesced 128B line per warp step
        float2 v = __ldg(&tin[s]); // random L2-resident gather
        ax += v.x;  ay += v.y;
    }
    // warp reduction
    #pragma unroll
    for (int off = 16; off > 0; off >>= 1) {
        ax += __shfl_xor_sync(0xFFFFFFFFu, ax, off);
        ay += __shfl_xor_sync(0xFFFFFFFFu, ay, off);
    }

    if (lane == 0) {
        float  ds = g_dis[n];
        float2 ts = tin[n];                     // self-loop term
        float b0 = __ldg(&bs[layer * 2 + 0]);
        float b1 = __ldg(&bs[layer * 2 + 1]);
        float hx = ds * (ax + ts.x) + b0;
        float hy = ds * (ay + ts.y) + b1;

        if (layer == NL - 1) {
            out[n]      = hx;
            out[NN + n] = hy;
        } else {
            const float* W = Ws + (layer + 1) * 4;
            float w00 = __ldg(&W[0]), w01 = __ldg(&W[1]);
            float w10 = __ldg(&W[2]), w11 = __ldg(&W[3]);
            g_t[inbuf ^ 1][n] = make_float2(ds * (hx * w00 + hy * w10),
                                            ds * (hx * w01 + hy * w11));
        }
    }
}

extern "C" void kernel_launch(void* const* d_in, const int* in_sizes, int n_in,
                              void* d_out, int out_size) {
    const float* x  = (const float*)d_in[0];
    const void*  ei = d_in[1];
    const float* Ws = (const float*)d_in[2];
    const float* bs = (const float*)d_in[3];
    float* out = (float*)d_out;

    const int TB = 256;
    const int NB_E = (NE + TB - 1) / TB;
    const int NB_W = (NN * 32 + TB - 1) / TB;   // warp-per-node grid

    k_detect<<<1, 32>>>((const unsigned int*)ei);
    k_zero<<<NB_N, TB>>>();
    k_deg<<<NB_E, TB>>>(ei);
    k_scan1<<<NB_N, TB>>>();
    k_scan2<<<1, 1024>>>();
    k_scan3<<<NB_N, TB>>>();
    k_fill<<<NB_E, TB>>>(ei);
    k_init<<<NB_N, TB>>>(x, Ws);

    int inbuf = 0;
    for (int l = 0; l < NL; l++) {
        k_layer<<<NB_W, TB>>>(Ws, bs, l, inbuf, out);
        inbuf ^= 1;
    }
}

// round 5
// speedup vs baseline: 1.0023x; 1.0023x over previous
#include <cuda_runtime.h>
#include <cstdint>

#define NN 200000
#define NE 6400000
#define NL 10
#define NB_N 782            // ceil(NN/256)
#define NBUCK 128
#define CSR_CAP (NE + 3 * NN)   // padded rows (<=3 pad entries per node)

// ---------------- scratch (static __device__, no allocs) -------------------
__device__ __align__(16) int g_csr[CSR_CAP];  // rank-space src ids, padded rows
__device__ int    g_prow[NN + 1];  // padded row pointers (rank order)
__device__ int    g_cursor[NN];    // fill cursors (rank order)
__device__ int    g_deg[NN];       // in-degree per node (orig id)
__device__ int    g_perm[NN];      // rank -> node
__device__ int    g_rank[NN];      // node -> rank
__device__ float  g_dis[NN];       // rsqrt(deg+1), rank order
__device__ float2 g_t[2][NN + 1];  // ping-pong t, rank order; [NN] = 0 sentinel
__device__ int    g_part[1024];    // scan partials
__device__ int    g_bcount[NBUCK]; // degree-bucket counts
__device__ int    g_bcur[NBUCK];   // degree-bucket cursors
__device__ int    g_is64;

// ---- dtype sniff: int64 indices < 2^31 have all-zero odd 32-bit words -----
__global__ void k_detect(const unsigned int* __restrict__ w) {
    int lane = threadIdx.x;
    unsigned int acc = 0;
    for (int i = 0; i < 32; i++) acc |= w[2 * (lane * 32 + i) + 1];
    unsigned mask = __ballot_sync(0xFFFFFFFFu, acc != 0);
    if (lane == 0) g_is64 = (mask == 0) ? 1 : 0;
}

__global__ void k_zero() {
    int i = blockIdx.x * blockDim.x + threadIdx.x;
    if (i < NN) g_deg[i] = 0;
    if (i < NBUCK) g_bcount[i] = 0;
}

// count in-degree at dst
__global__ void k_deg(const void* __restrict__ ei_raw) {
    int e = blockIdx.x * blockDim.x + threadIdx.x;
    if (e >= NE) return;
    int d;
    if (g_is64) d = (int)((const long long*)ei_raw)[NE + e];
    else        d = ((const int*)ei_raw)[NE + e];
    atomicAdd(&g_deg[d], 1);
}

// ---- counting sort of nodes by (clamped) degree ----------------------------
__global__ void k_hist() {
    __shared__ int sh[NBUCK];
    if (threadIdx.x < NBUCK) sh[threadIdx.x] = 0;
    __syncthreads();
    int i = blockIdx.x * blockDim.x + threadIdx.x;
    if (i < NN) {
        int b = min(g_deg[i], NBUCK - 1);
        atomicAdd(&sh[b], 1);
    }
    __syncthreads();
    if (threadIdx.x < NBUCK && sh[threadIdx.x])
        atomicAdd(&g_bcount[threadIdx.x], sh[threadIdx.x]);
}

__global__ void k_bscan() {      // single block of 128: exclusive scan
    __shared__ int sm[NBUCK];
    int t = threadIdx.x;
    int v = g_bcount[t];
    sm[t] = v;
    __syncthreads();
    for (int off = 1; off < NBUCK; off <<= 1) {
        int u = (t >= off) ? sm[t - off] : 0;
        __syncthreads();
        sm[t] += u;
        __syncthreads();
    }
    g_bcur[t] = sm[t] - v;       // exclusive
}

__global__ void k_perm() {
    int n = blockIdx.x * blockDim.x + threadIdx.x;
    if (n >= NN) return;
    int b = min(g_deg[n], NBUCK - 1);
    int r = atomicAdd(&g_bcur[b], 1);
    g_perm[r] = n;
    g_rank[n] = r;
}

// ---- 3-kernel exclusive scan of padded row lengths (rank order) -----------
__device__ __forceinline__ int plen_of(int r) {
    int d = g_deg[g_perm[r]];
    return (d + 3) & ~3;                    // pad to multiple of 4
}

__global__ void k_scan1() {
    __shared__ int sm[256];
    int i = blockIdx.x * 256 + threadIdx.x;
    int v = (i < NN) ? plen_of(i) : 0;
    sm[threadIdx.x] = v;
    __syncthreads();
    for (int off = 1; off < 256; off <<= 1) {
        int t = (threadIdx.x >= off) ? sm[threadIdx.x - off] : 0;
        __syncthreads();
        sm[threadIdx.x] += t;
        __syncthreads();
    }
    if (i < NN) g_prow[i] = sm[threadIdx.x] - v;
    if (threadIdx.x == 255) g_part[blockIdx.x] = sm[255];
}

__global__ void k_scan2() {
    __shared__ int sm[1024];
    int t = threadIdx.x;
    int v = (t < NB_N) ? g_part[t] : 0;
    sm[t] = v;
    __syncthreads();
    for (int off = 1; off < 1024; off <<= 1) {
        int u = (t >= off) ? sm[t - off] : 0;
        __syncthreads();
        sm[t] += u;
        __syncthreads();
    }
    if (t < NB_N) g_part[t] = sm[t] - v;
}

__global__ void k_scan3() {
    int i = blockIdx.x * blockDim.x + threadIdx.x;
    if (i < NN) {
        int r = g_prow[i] + g_part[i >> 8];
        g_prow[i] = r;
        g_cursor[i] = r;
    }
    if (i == 0) {
        // total padded length
        int last = NN - 1;
        // computed again on host side not possible; set below in k_pad via cursor
        g_prow[NN] = 0;  // fixed up in k_fin
    }
}

__global__ void k_fin() {        // g_prow[NN] = prow[NN-1] + plen(NN-1)
    g_prow[NN] = g_prow[NN - 1] + plen_of(NN - 1);
}

// scatter rank-space src ids into rank-grouped CSR
__global__ void k_fill(const void* __restrict__ ei_raw) {
    int e = blockIdx.x * blockDim.x + threadIdx.x;
    if (e >= NE) return;
    int s, d;
    if (g_is64) {
        const long long* ei = (const long long*)ei_raw;
        s = (int)ei[e];  d = (int)ei[NE + e];
    } else {
        const int* ei = (const int*)ei_raw;
        s = ei[e];       d = ei[NE + e];
    }
    int r = g_rank[d];
    int pos = atomicAdd(&g_cursor[r], 1);
    g_csr[pos] = g_rank[s];
}

// pad row tails with the zero-sentinel index NN
__global__ void k_pad() {
    int r = blockIdx.x * blockDim.x + threadIdx.x;
    if (r >= NN) return;
    int d   = g_deg[g_perm[r]];
    int beg = g_prow[r] + d;
    int end = g_prow[r] + ((d + 3) & ~3);
    for (int j = beg; j < end; j++) g_csr[j] = NN;
}

// dis = rsqrt(deg+1); t0 = dis * (x @ W0)   (rank order)
__global__ void k_init(const float* __restrict__ x, const float* __restrict__ Ws) {
    int r = blockIdx.x * blockDim.x + threadIdx.x;
    if (r >= NN) return;
    int n = g_perm[r];
    float ds = rsqrtf((float)(g_deg[n] + 1));
    g_dis[r] = ds;
    float w00 = __ldg(&Ws[0]), w01 = __ldg(&Ws[1]);
    float w10 = __ldg(&Ws[2]), w11 = __ldg(&Ws[3]);
    float hx = x[2 * n], hy = x[2 * n + 1];
    g_t[0][r] = make_float2(ds * (hx * w00 + hy * w10),
                            ds * (hx * w01 + hy * w11));
    if (r == 0) {                          // zero sentinels once
        g_t[0][NN] = make_float2(0.f, 0.f);
        g_t[1][NN] = make_float2(0.f, 0.f);
    }
}

// Fused layer, thread-per-node in DEGREE-SORTED order:
// int4 CSR reads (padded rows), random rank-space gathers, coalesced epilogue.
__global__ void __launch_bounds__(256) k_layer(
        const float* __restrict__ Ws, const float* __restrict__ bs,
        int layer, int inbuf, float* __restrict__ out) {
    int r = blockIdx.x * blockDim.x + threadIdx.x;
    if (r >= NN) return;

    const float2* __restrict__ tin = g_t[inbuf];
    int beg = __ldg(&g_prow[r]);
    int end = __ldg(&g_prow[r + 1]);
    const int4* p = (const int4*)&g_csr[beg];
    int steps = (end - beg) >> 2;

    float ax = 0.f, ay = 0.f;
    #pragma unroll 2
    for (int i = 0; i < steps; i++) {
        int4 s4 = __ldg(&p[i]);
        float2 v0 = __ldg(&tin[s4.x]);
        float2 v1 = __ldg(&tin[s4.y]);
        float2 v2 = __ldg(&tin[s4.z]);
        float2 v3 = __ldg(&tin[s4.w]);
        ax += (v0.x + v1.x) + (v2.x + v3.x);
        ay += (v0.y + v1.y) + (v2.y + v3.y);
    }

    float  ds = g_dis[r];
    float2 ts = tin[r];                      // self-loop term
    float b0 = __ldg(&bs[layer * 2 + 0]);
    float b1 = __ldg(&bs[layer * 2 + 1]);
    float hx = ds * (ax + ts.x) + b0;
    float hy = ds * (ay + ts.y) + b1;

    if (layer == NL - 1) {
        int n = __ldg(&g_perm[r]);
        out[n]      = hx;
        out[NN + n] = hy;
    } else {
        const float* W = Ws + (layer + 1) * 4;
        float w00 = __ldg(&W[0]), w01 = __ldg(&W[1]);
        float w10 = __ldg(&W[2]), w11 = __ldg(&W[3]);
        g_t[inbuf ^ 1][r] = make_float2(ds * (hx * w00 + hy * w10),
                                        ds * (hx * w01 + hy * w11));
    }
}

extern "C" void kernel_launch(void* const* d_in, const int* in_sizes, int n_in,
                              void* d_out, int out_size) {
    const float* x  = (const float*)d_in[0];
    const void*  ei = d_in[1];
    const float* Ws = (const float*)d_in[2];
    const float* bs = (const float*)d_in[3];
    float* out = (float*)d_out;

    const int TB = 256;
    const int NB_E = (NE + TB - 1) / TB;

    k_detect<<<1, 32>>>((const unsigned int*)ei);
    k_zero<<<NB_N, TB>>>();
    k_deg<<<NB_E, TB>>>(ei);
    k_hist<<<NB_N, TB>>>();
    k_bscan<<<1, NBUCK>>>();
    k_perm<<<NB_N, TB>>>();
    k_scan1<<<NB_N, TB>>>();
    k_scan2<<<1, 1024>>>();
    k_scan3<<<NB_N, TB>>>();
    k_fin<<<1, 1>>>();
    k_fill<<<NB_E, TB>>>(ei);
    k_pad<<<NB_N, TB>>>();
    k_init<<<NB_N, TB>>>(x, Ws);

    int inbuf = 0;
    for (int l = 0; l < NL; l++) {
        k_layer<<<NB_N, TB>>>(Ws, bs, l, inbuf, out);
        inbuf ^= 1;
    }
}

// round 6
// speedup vs baseline: 1.1501x; 1.1474x over previous
#include <cuda_runtime.h>
#include <cstdint>

#define NN 200000
#define NE 6400000
#define NL 10
#define TB 256
#define NB_N 782                 // ceil(NN/TB)
#define CSR_CAP (NE + 3 * NN)

// ---------------- scratch (static __device__, no allocs) -------------------
__device__ __align__(16) int g_csr[CSR_CAP]; // src ids, dst rows padded to 4
__device__ int    g_row[NN + 1];   // padded row pointers (node order)
__device__ int    g_cursor[NN];    // fill cursors
__device__ int    g_deg[NN];       // in-degree (excl. self-loop)
__device__ float  g_dis[NN];       // rsqrt(deg+1)
__device__ float2 g_t[2][NN + 1];  // ping-pong t; [NN] = zero sentinel
__device__ int    g_flag[NB_N];    // lookback: 0 none / 1 partial / 2 full
__device__ int    g_agg[NB_N];
__device__ int    g_incl[NB_N];
__device__ int    g_is64;

// ---- launch 1: dtype sniff + zero degrees/flags ---------------------------
__global__ void k_prep(const unsigned int* __restrict__ w) {
    int i = blockIdx.x * TB + threadIdx.x;
    if (i < NN) g_deg[i] = 0;
    if (i < NB_N) g_flag[i] = 0;
    if (blockIdx.x == 0 && threadIdx.x < 32) {
        // int64 indices < 2^31 -> all odd 32-bit words zero; int32 data won't be
        unsigned int acc = 0;
        for (int j = 0; j < 32; j++) acc |= w[2 * (threadIdx.x * 32 + j) + 1];
        unsigned mask = __ballot_sync(0xFFFFFFFFu, acc != 0);
        if (threadIdx.x == 0) g_is64 = (mask == 0) ? 1 : 0;
    }
}

// ---- launch 2: count in-degree at dst --------------------------------------
__global__ void k_deg(const void* __restrict__ ei_raw) {
    int e = blockIdx.x * TB + threadIdx.x;
    if (e >= NE) return;
    int d;
    if (g_is64) d = (int)((const long long*)ei_raw)[NE + e];
    else        d = ((const int*)ei_raw)[NE + e];
    atomicAdd(&g_deg[d], 1);
}

// ---- launch 3: single-pass exclusive scan of padded row lengths -----------
// (decoupled lookback; all 782 blocks are co-resident so spin is safe)
__global__ void k_scan() {
    __shared__ int sm[TB];
    __shared__ int s_prefix;
    int bid = blockIdx.x;
    int i = bid * TB + threadIdx.x;
    int v = (i < NN) ? ((g_deg[i] + 3) & ~3) : 0;

    sm[threadIdx.x] = v;
    __syncthreads();
    for (int off = 1; off < TB; off <<= 1) {
        int t = (threadIdx.x >= off) ? sm[threadIdx.x - off] : 0;
        __syncthreads();
        sm[threadIdx.x] += t;
        __syncthreads();
    }
    int incl = sm[threadIdx.x];
    int bsum = sm[TB - 1];

    if (threadIdx.x == 0) {
        if (bid == 0) {
            g_incl[0] = bsum;
            __threadfence();
            atomicExch(&g_flag[0], 2);
            s_prefix = 0;
        } else {
            g_agg[bid] = bsum;
            __threadfence();
            atomicExch(&g_flag[bid], 1);
            int ex = 0;
            for (int j = bid - 1; j >= 0; ) {
                int f;
                do { f = atomicAdd(&g_flag[j], 0); } while (f == 0);
                __threadfence();
                if (f == 2) { ex += g_incl[j]; break; }
                ex += g_agg[j];
                j--;
            }
            g_incl[bid] = ex + bsum;
            __threadfence();
            atomicExch(&g_flag[bid], 2);
            s_prefix = ex;
        }
    }
    __syncthreads();
    if (i < NN) {
        int r = s_prefix + incl - v;   // exclusive
        g_row[i] = r;
        g_cursor[i] = r;
        if (i == NN - 1) g_row[NN] = s_prefix + incl;
    }
}

// ---- launch 4: scatter src ids into rows + pad tails with sentinel --------
__global__ void k_fillpad(const void* __restrict__ ei_raw) {
    int id = blockIdx.x * TB + threadIdx.x;
    if (id < NE) {
        int s, d;
        if (g_is64) {
            const long long* ei = (const long long*)ei_raw;
            s = (int)ei[id];  d = (int)ei[NE + id];
        } else {
            const int* ei = (const int*)ei_raw;
            s = ei[id];       d = ei[NE + id];
        }
        int pos = atomicAdd(&g_cursor[d], 1);
        g_csr[pos] = s;
    } else if (id < NE + NN) {
        int n = id - NE;
        int dg  = g_deg[n];
        int beg = g_row[n] + dg;
        int end = g_row[n] + ((dg + 3) & ~3);
        for (int j = beg; j < end; j++) g_csr[j] = NN;   // zero sentinel
    }
}

// ---- launch 5: dis = rsqrt(deg+1); t0 = dis * (x @ W0) ---------------------
__global__ void k_init(const float* __restrict__ x, const float* __restrict__ Ws) {
    int n = blockIdx.x * TB + threadIdx.x;
    if (n >= NN) return;
    float ds = rsqrtf((float)(g_deg[n] + 1));
    g_dis[n] = ds;
    float w00 = __ldg(&Ws[0]), w01 = __ldg(&Ws[1]);
    float w10 = __ldg(&Ws[2]), w11 = __ldg(&Ws[3]);
    float hx = x[2 * n], hy = x[2 * n + 1];
    g_t[0][n] = make_float2(ds * (hx * w00 + hy * w10),
                            ds * (hx * w01 + hy * w11));
    if (n == 0) {
        g_t[0][NN] = make_float2(0.f, 0.f);
        g_t[1][NN] = make_float2(0.f, 0.f);
    }
}

// ---- launches 6..15: fused GCN layer, thread-per-node, int4 CSR ------------
__global__ void __launch_bounds__(TB) k_layer(
        const float* __restrict__ Ws, const float* __restrict__ bs,
        int layer, int inbuf, float* __restrict__ out) {
    int n = blockIdx.x * TB + threadIdx.x;
    if (n >= NN) return;

    const float2* __restrict__ tin = g_t[inbuf];
    int beg = __ldg(&g_row[n]);
    int end = __ldg(&g_row[n + 1]);
    const int4* p = (const int4*)(g_csr + beg);
    int steps = (end - beg) >> 2;

    float ax = 0.f, ay = 0.f, cx = 0.f, cy = 0.f;
    int i = 0;
    for (; i + 1 < steps; i += 2) {                 // 8 independent gathers
        int4 a = __ldg(&p[i]);
        int4 b = __ldg(&p[i + 1]);
        float2 v0 = __ldg(&tin[a.x]);
        float2 v1 = __ldg(&tin[a.y]);
        float2 v2 = __ldg(&tin[a.z]);
        float2 v3 = __ldg(&tin[a.w]);
        float2 u0 = __ldg(&tin[b.x]);
        float2 u1 = __ldg(&tin[b.y]);
        float2 u2 = __ldg(&tin[b.z]);
        float2 u3 = __ldg(&tin[b.w]);
        ax += (v0.x + v1.x) + (v2.x + v3.x);
        ay += (v0.y + v1.y) + (v2.y + v3.y);
        cx += (u0.x + u1.x) + (u2.x + u3.x);
        cy += (u0.y + u1.y) + (u2.y + u3.y);
    }
    if (i < steps) {
        int4 a = __ldg(&p[i]);
        float2 v0 = __ldg(&tin[a.x]);
        float2 v1 = __ldg(&tin[a.y]);
        float2 v2 = __ldg(&tin[a.z]);
        float2 v3 = __ldg(&tin[a.w]);
        ax += (v0.x + v1.x) + (v2.x + v3.x);
        ay += (v0.y + v1.y) + (v2.y + v3.y);
    }
    ax += cx;  ay += cy;

    float  ds = g_dis[n];
    float2 ts = tin[n];                    // self-loop term
    float b0 = __ldg(&bs[layer * 2 + 0]);
    float b1 = __ldg(&bs[layer * 2 + 1]);
    float hx = ds * (ax + ts.x) + b0;
    float hy = ds * (ay + ts.y) + b1;

    if (layer == NL - 1) {
        out[n]      = hx;                  // transposed output, coalesced
        out[NN + n] = hy;
    } else {
        const float* W = Ws + (layer + 1) * 4;
        float w00 = __ldg(&W[0]), w01 = __ldg(&W[1]);
        float w10 = __ldg(&W[2]), w11 = __ldg(&W[3]);
        g_t[inbuf ^ 1][n] = make_float2(ds * (hx * w00 + hy * w10),
                                        ds * (hx * w01 + hy * w11));
    }
}

extern "C" void kernel_launch(void* const* d_in, const int* in_sizes, int n_in,
                              void* d_out, int out_size) {
    const float* x  = (const float*)d_in[0];
    const void*  ei = d_in[1];
    const float* Ws = (const float*)d_in[2];
    const float* bs = (const float*)d_in[3];
    float* out = (float*)d_out;

    const int NB_E  = (NE + TB - 1) / TB;
    const int NB_FP = (NE + NN + TB - 1) / TB;

    k_prep<<<NB_N, TB>>>((const unsigned int*)ei);   // #1
    k_deg<<<NB_E, TB>>>(ei);                         // #2
    k_scan<<<NB_N, TB>>>();                          // #3
    k_fillpad<<<NB_FP, TB>>>(ei);                    // #4
    k_init<<<NB_N, TB>>>(x, Ws);                     // #5

    int inbuf = 0;
    for (int l = 0; l < NL; l++) {                   // #6..15
        k_layer<<<NB_N, TB>>>(Ws, bs, l, inbuf, out);
        inbuf ^= 1;
    }
}

// round 7
// speedup vs baseline: 1.2170x; 1.0582x over previous
#include <cuda_runtime.h>
#include <cstdint>

#define NN 200000
#define NE 6400000
#define NL 10
#define TB 256
#define NB_N 782                 // ceil(NN/TB)
#define CSR_CAP (NE + 3 * NN)
#define SM_INTS 10240            // 40KB SMEM CSR stage (mean 8576 ints, sigma~90)

// ---------------- scratch (static __device__, no allocs) -------------------
__device__ __align__(16) int g_csr[CSR_CAP]; // src ids, dst rows padded to 4
__device__ int    g_row[NN + 1];   // padded row pointers (node order)
__device__ int    g_cursor[NN];    // fill cursors
__device__ int    g_deg[NN];       // in-degree (excl. self-loop)
__device__ float  g_dis[NN];       // rsqrt(deg+1)
__device__ float2 g_t[2][NN + 1];  // ping-pong t; [NN] = zero sentinel
__device__ int    g_flag[NB_N];    // lookback: 0 none / 1 partial / 2 full
__device__ int    g_agg[NB_N];
__device__ int    g_incl[NB_N];
__device__ int    g_is64;

// ---- launch 1: dtype sniff + zero degrees/flags ---------------------------
__global__ void k_prep(const unsigned int* __restrict__ w) {
    int i = blockIdx.x * TB + threadIdx.x;
    if (i < NN) g_deg[i] = 0;
    if (i < NB_N) g_flag[i] = 0;
    if (blockIdx.x == 0 && threadIdx.x < 32) {
        // int64 indices < 2^31 -> all odd 32-bit words zero; int32 data won't be
        unsigned int acc = 0;
        for (int j = 0; j < 32; j++) acc |= w[2 * (threadIdx.x * 32 + j) + 1];
        unsigned mask = __ballot_sync(0xFFFFFFFFu, acc != 0);
        if (threadIdx.x == 0) g_is64 = (mask == 0) ? 1 : 0;
    }
}

// ---- launch 2: count in-degree at dst --------------------------------------
__global__ void k_deg(const void* __restrict__ ei_raw) {
    int e = blockIdx.x * TB + threadIdx.x;
    if (e >= NE) return;
    int d;
    if (g_is64) d = (int)((const long long*)ei_raw)[NE + e];
    else        d = ((const int*)ei_raw)[NE + e];
    atomicAdd(&g_deg[d], 1);
}

// ---- launch 3: single-pass exclusive scan of padded row lengths,
//      fused with dis/t0 init (decoupled lookback; 782 blocks co-resident) --
__global__ void k_scan_init(const float* __restrict__ x,
                            const float* __restrict__ Ws) {
    __shared__ int sm[TB];
    __shared__ int s_prefix;
    int bid = blockIdx.x;
    int i = bid * TB + threadIdx.x;
    int dg = (i < NN) ? g_deg[i] : 0;
    int v  = (i < NN) ? ((dg + 3) & ~3) : 0;

    sm[threadIdx.x] = v;
    __syncthreads();
    for (int off = 1; off < TB; off <<= 1) {
        int t = (threadIdx.x >= off) ? sm[threadIdx.x - off] : 0;
        __syncthreads();
        sm[threadIdx.x] += t;
        __syncthreads();
    }
    int incl = sm[threadIdx.x];
    int bsum = sm[TB - 1];

    if (threadIdx.x == 0) {
        if (bid == 0) {
            g_incl[0] = bsum;
            __threadfence();
            atomicExch(&g_flag[0], 2);
            s_prefix = 0;
        } else {
            g_agg[bid] = bsum;
            __threadfence();
            atomicExch(&g_flag[bid], 1);
            int ex = 0;
            for (int j = bid - 1; j >= 0; ) {
                int f;
                do { f = atomicAdd(&g_flag[j], 0); } while (f == 0);
                __threadfence();
                if (f == 2) { ex += g_incl[j]; break; }
                ex += g_agg[j];
                j--;
            }
            g_incl[bid] = ex + bsum;
            __threadfence();
            atomicExch(&g_flag[bid], 2);
            s_prefix = ex;
        }
    }
    __syncthreads();
    if (i < NN) {
        int r = s_prefix + incl - v;   // exclusive
        g_row[i] = r;
        g_cursor[i] = r;
        if (i == NN - 1) g_row[NN] = s_prefix + incl;

        // fused init: dis = rsqrt(deg+1); t0 = dis * (x @ W0)
        float ds = rsqrtf((float)(dg + 1));
        g_dis[i] = ds;
        float w00 = __ldg(&Ws[0]), w01 = __ldg(&Ws[1]);
        float w10 = __ldg(&Ws[2]), w11 = __ldg(&Ws[3]);
        float2 h = __ldg(&((const float2*)x)[i]);
        g_t[0][i] = make_float2(ds * (h.x * w00 + h.y * w10),
                                ds * (h.x * w01 + h.y * w11));
        if (i == 0) {
            g_t[0][NN] = make_float2(0.f, 0.f);
            g_t[1][NN] = make_float2(0.f, 0.f);
        }
    }
}

// ---- launch 4: scatter src ids into rows + pad tails with sentinel --------
__global__ void k_fillpad(const void* __restrict__ ei_raw) {
    int id = blockIdx.x * TB + threadIdx.x;
    if (id < NE) {
        int s, d;
        if (g_is64) {
            const long long* ei = (const long long*)ei_raw;
            s = (int)ei[id];  d = (int)ei[NE + id];
        } else {
            const int* ei = (const int*)ei_raw;
            s = ei[id];       d = ei[NE + id];
        }
        int pos = atomicAdd(&g_cursor[d], 1);
        g_csr[pos] = s;
    } else if (id < NE + NN) {
        int n = id - NE;
        int dg  = g_deg[n];
        int beg = g_row[n] + dg;
        int end = g_row[n] + ((dg + 3) & ~3);
        for (int j = beg; j < end; j++) g_csr[j] = NN;   // zero sentinel
    }
}

// ---- launches 5..14: fused GCN layer, thread-per-node, SMEM-staged CSR ----
__global__ void __launch_bounds__(TB) k_layer(
        const float* __restrict__ Ws, const float* __restrict__ bs,
        int layer, int inbuf, float* __restrict__ out) {
    __shared__ __align__(16) int s_csr[SM_INTS];
    int nb  = blockIdx.x * TB;
    int tid = threadIdx.x;
    int n   = nb + tid;
    int lastn = min(nb + TB, NN);
    int sbeg = __ldg(&g_row[nb]);
    int send = __ldg(&g_row[lastn]);
    int cnt  = send - sbeg;                 // multiple of 4, ~8.6K ints typ.
    bool staged = (cnt <= SM_INTS);

    if (staged) {                           // coalesced block-wide CSR stage
        const int4* src4 = (const int4*)g_csr + (sbeg >> 2);
        int4* dst4 = (int4*)s_csr;
        int n4 = cnt >> 2;
        for (int i = tid; i < n4; i += TB) dst4[i] = __ldg(&src4[i]);
    }
    __syncthreads();
    if (n >= NN) return;

    const float2* __restrict__ tin = g_t[inbuf];
    int beg = __ldg(&g_row[n]);
    int end = __ldg(&g_row[n + 1]);
    float ax = 0.f, ay = 0.f, cx = 0.f, cy = 0.f;

    if (staged) {
        const int4* p = (const int4*)s_csr + ((beg - sbeg) >> 2);
        int steps = (end - beg) >> 2;
        int i = 0;
        for (; i + 1 < steps; i += 2) {     // 8 independent gathers in flight
            int4 a = p[i];
            int4 b = p[i + 1];
            float2 v0 = __ldg(&tin[a.x]);
            float2 v1 = __ldg(&tin[a.y]);
            float2 v2 = __ldg(&tin[a.z]);
            float2 v3 = __ldg(&tin[a.w]);
            float2 u0 = __ldg(&tin[b.x]);
            float2 u1 = __ldg(&tin[b.y]);
            float2 u2 = __ldg(&tin[b.z]);
            float2 u3 = __ldg(&tin[b.w]);
            ax += (v0.x + v1.x) + (v2.x + v3.x);
            ay += (v0.y + v1.y) + (v2.y + v3.y);
            cx += (u0.x + u1.x) + (u2.x + u3.x);
            cy += (u0.y + u1.y) + (u2.y + u3.y);
        }
        if (i < steps) {
            int4 a = p[i];
            float2 v0 = __ldg(&tin[a.x]);
            float2 v1 = __ldg(&tin[a.y]);
            float2 v2 = __ldg(&tin[a.z]);
            float2 v3 = __ldg(&tin[a.w]);
            ax += (v0.x + v1.x) + (v2.x + v3.x);
            ay += (v0.y + v1.y) + (v2.y + v3.y);
        }
    } else {                                // ~never taken (>15 sigma); safe path
        for (int j = beg; j < end; j++) {
            float2 v = __ldg(&tin[g_csr[j]]);
            ax += v.x;  ay += v.y;
        }
    }
    ax += cx;  ay += cy;

    float  ds = g_dis[n];
    float2 ts = tin[n];                     // self-loop term
    float b0 = __ldg(&bs[layer * 2 + 0]);
    float b1 = __ldg(&bs[layer * 2 + 1]);
    float hx = ds * (ax + ts.x) + b0;
    float hy = ds * (ay + ts.y) + b1;

    if (layer == NL - 1) {
        out[n]      = hx;                   // transposed output, coalesced
        out[NN + n] = hy;
    } else {
        const float* W = Ws + (layer + 1) * 4;
        float w00 = __ldg(&W[0]), w01 = __ldg(&W[1]);
        float w10 = __ldg(&W[2]), w11 = __ldg(&W[3]);
        g_t[inbuf ^ 1][n] = make_float2(ds * (hx * w00 + hy * w10),
                                        ds * (hx * w01 + hy * w11));
    }
}

extern "C" void kernel_launch(void* const* d_in, const int* in_sizes, int n_in,
                              void* d_out, int out_size) {
    const float* x  = (const float*)d_in[0];
    const void*  ei = d_in[1];
    const float* Ws = (const float*)d_in[2];
    const float* bs = (const float*)d_in[3];
    float* out = (float*)d_out;

    const int NB_E  = (NE + TB - 1) / TB;
    const int NB_FP = (NE + NN + TB - 1) / TB;

    k_prep<<<NB_N, TB>>>((const unsigned int*)ei);   // #1
    k_deg<<<NB_E, TB>>>(ei);                         // #2
    k_scan_init<<<NB_N, TB>>>(x, Ws);                // #3
    k_fillpad<<<NB_FP, TB>>>(ei);                    // #4

    int inbuf = 0;
    for (int l = 0; l < NL; l++) {                   // #5..14
        k_layer<<<NB_N, TB>>>(Ws, bs, l, inbuf, out);
        inbuf ^= 1;
    }
}